// round 1
// baseline (speedup 1.0000x reference)
#include <cuda_runtime.h>
#include <math.h>

// Problem constants
#define NB   4
#define CH   16
#define HH   256
#define WW   256
#define HWSZ 65536
#define INV_TEMP 10.0f
#define EPSV 1e-6f

// Channels-last normalized features: [n][i][j][c], 4*65536*16 floats = 16 MB
__device__ float g_fn[(size_t)NB * HWSZ * CH];
// Partial sums
__device__ float g_lp[512];
__device__ float g_dp[256];

// ---------------------------------------------------------------------------
// Kernel 1: L2-normalize over C and transpose NCHW -> N(HW)C (channels-last)
// ---------------------------------------------------------------------------
__global__ void k_norm(const float* __restrict__ f) {
    int idx = blockIdx.x * blockDim.x + threadIdx.x;  // 0 .. N*HW-1
    int n   = idx >> 16;
    int pix = idx & 65535;
    const float* b = f + (size_t)n * CH * HWSZ + pix;
    float v[CH];
    float ss = 0.f;
#pragma unroll
    for (int c = 0; c < CH; c++) {
        v[c] = b[(size_t)c * HWSZ];
        ss = fmaf(v[c], v[c], ss);
    }
    float inv = 1.0f / fmaxf(sqrtf(ss), 1e-12f);
    float4* o = (float4*)(g_fn + (size_t)idx * CH);
#pragma unroll
    for (int c4 = 0; c4 < 4; c4++) {
        o[c4] = make_float4(v[c4*4+0]*inv, v[c4*4+1]*inv,
                            v[c4*4+2]*inv, v[c4*4+3]*inv);
    }
}

// ---------------------------------------------------------------------------
// Kernel 2: local 11x11 contrastive term.
// Block = (n, 2 consecutive rows). 512 threads, one pixel each.
// Smem: 12 halo rows, channels-last with chunk XOR swizzle (conflict-free
// LDS.128 for any uniform column shift q), plus planar label rows.
// ---------------------------------------------------------------------------
__global__ void __launch_bounds__(512, 1)
k_local(const int* __restrict__ labels) {
    extern __shared__ float sm[];
    float* sF = sm;                      // 12 * 4096 floats (12 rows * 256 px * 16c)
    int*   sL = (int*)(sm + 12 * 4096);  // 12 * 256 ints

    const int bx = blockIdx.x;           // 0..511
    const int n  = bx >> 7;
    const int i0 = (bx & 127) << 1;      // first of 2 center rows
    const int t  = threadIdx.x;

    // ---- load feature halo tile (rows i0-5 .. i0+6) ----
    {
        const float4* src = (const float4*)(g_fn + (size_t)n * HWSZ * CH);
#pragma unroll
        for (int k = 0; k < 24; k++) {
            int lin = t + (k << 9);          // 0..12287 float4s
            int rr  = lin >> 10;             // slot 0..11
            int row = i0 - 5 + rr;
            if ((unsigned)row < 256u) {
                int pxc = lin & 1023;
                int px  = pxc >> 2;
                int c4  = pxc & 3;
                float4 v = src[((row << 8) + px) * 4 + c4];
                int c4s = c4 ^ ((px >> 1) & 3);   // chunk swizzle
                *(float4*)&sF[(rr << 12) + (px << 4) + (c4s << 2)] = v;
            }
        }
        const int* ls = labels + n * HWSZ;
#pragma unroll
        for (int k = 0; k < 6; k++) {
            int lin = t + (k << 9);
            if (lin < 3072) {
                int rr = lin >> 8, px = lin & 255;
                int row = i0 - 5 + rr;
                sL[lin] = ((unsigned)row < 256u) ? ls[(row << 8) + px]
                                                 : (int)0x80000000;
            }
        }
    }
    __syncthreads();

    const int r  = t >> 8;       // 0/1: which center row (warp-uniform)
    const int j  = t & 255;
    const int ci = i0 + r;
    const int cslot = r + 5;

    // center vector
    float cv[CH];
#pragma unroll
    for (int c4 = 0; c4 < 4; c4++) {
        float4 v = *(float4*)&sF[(cslot << 12) + (j << 4)
                                 + ((c4 ^ ((j >> 1) & 3)) << 2)];
        cv[c4*4+0] = v.x; cv[c4*4+1] = v.y; cv[c4*4+2] = v.z; cv[c4*4+3] = v.w;
    }
    const int clab = sL[(cslot << 8) + j];

    float S = 0.f, Ls = 0.f, Ms = 0.f;
#pragma unroll 1
    for (int p = -5; p <= 5; p++) {
        int row = ci + p;
        if ((unsigned)row >= 256u) continue;       // warp-uniform
        const int slotF = (cslot + p) << 12;
        const int slotL = (cslot + p) << 8;
#pragma unroll
        for (int q = -5; q <= 5; q++) {
            int jq  = j + q;
            bool vld = (unsigned)jq < 256u;
            int jc  = vld ? jq : (jq < 0 ? 0 : 255);   // clamped (branchless)
            const float* nb = &sF[slotF + (jc << 4)];
            int s3 = (jc >> 1) & 3;
            float4 a0 = *(const float4*)(nb + ((0 ^ s3) << 2));
            float4 a1 = *(const float4*)(nb + ((1 ^ s3) << 2));
            float4 a2 = *(const float4*)(nb + ((2 ^ s3) << 2));
            float4 a3 = *(const float4*)(nb + ((3 ^ s3) << 2));
            float d0 = cv[0]  * a0.x; d0 = fmaf(cv[1],  a0.y, d0);
            d0 = fmaf(cv[2],  a0.z, d0); d0 = fmaf(cv[3],  a0.w, d0);
            float d1 = cv[4]  * a1.x; d1 = fmaf(cv[5],  a1.y, d1);
            d1 = fmaf(cv[6],  a1.z, d1); d1 = fmaf(cv[7],  a1.w, d1);
            float d2 = cv[8]  * a2.x; d2 = fmaf(cv[9],  a2.y, d2);
            d2 = fmaf(cv[10], a2.z, d2); d2 = fmaf(cv[11], a2.w, d2);
            float d3 = cv[12] * a3.x; d3 = fmaf(cv[13], a3.y, d3);
            d3 = fmaf(cv[14], a3.z, d3); d3 = fmaf(cv[15], a3.w, d3);
            float dt    = (d0 + d1) + (d2 + d3);
            float logit = dt * INV_TEMP;
            bool  ok    = vld && (sL[slotL + jc] == clab);
            float e     = __expf(logit);
            if (ok) { S += e; Ls += logit; Ms += 1.0f; }
        }
    }

    float contrib = fmaf(Ms, __logf(S + EPSV), -Ls);
    int chh = 11 - max(0, 5 - ci) - max(0, ci - 250);
    int cww = 11 - max(0, 5 - j)  - max(0, j  - 250);
    float val = contrib / (4.0f * (float)(chh * cww) * 65536.0f);

    // block tree reduction (deterministic)
    __syncthreads();
    sm[t] = val;
    __syncthreads();
#pragma unroll 1
    for (int s = 256; s > 0; s >>= 1) {
        if (t < s) sm[t] += sm[t + s];
        __syncthreads();
    }
    if (t == 0) g_lp[bx] = sm[0];
}

// ---------------------------------------------------------------------------
// Kernel 3: directional term. One thread per (i,j), loops n,k.
// ---------------------------------------------------------------------------
__global__ void k_dir(const int* __restrict__ labels,
                      const int* __restrict__ dirs) {
    int tid = blockIdx.x * 256 + threadIdx.x;   // pixel index i*256+j
    int i = tid >> 8, j = tid & 255;

    int off[NB], lc[NB];
#pragma unroll
    for (int k = 0; k < NB; k++) {
        int di = dirs[(k * 2 + 0) * HWSZ + tid];
        int dj = dirs[(k * 2 + 1) * HWSZ + tid];
        off[k] = ((i + di) << 8) + (j + dj);    // already clipped in-range
        lc[k]  = labels[k * HWSZ + tid];
    }

    float sum = 0.f;
#pragma unroll 1
    for (int nn = 0; nn < NB; nn++) {
        const float4* base = (const float4*)(g_fn + (size_t)nn * HWSZ * CH);
        float cv[CH];
#pragma unroll
        for (int c4 = 0; c4 < 4; c4++) {
            float4 v = base[tid * 4 + c4];
            cv[c4*4+0] = v.x; cv[c4*4+1] = v.y; cv[c4*4+2] = v.z; cv[c4*4+3] = v.w;
        }
        float lg[NB]; bool mk[NB]; float S = 0.f;
#pragma unroll
        for (int k = 0; k < NB; k++) {
            float d0 = 0.f, d1 = 0.f, d2 = 0.f, d3 = 0.f;
            float4 a0 = base[off[k] * 4 + 0];
            float4 a1 = base[off[k] * 4 + 1];
            float4 a2 = base[off[k] * 4 + 2];
            float4 a3 = base[off[k] * 4 + 3];
            d0 = fmaf(cv[0],  a0.x, d0); d0 = fmaf(cv[1],  a0.y, d0);
            d0 = fmaf(cv[2],  a0.z, d0); d0 = fmaf(cv[3],  a0.w, d0);
            d1 = fmaf(cv[4],  a1.x, d1); d1 = fmaf(cv[5],  a1.y, d1);
            d1 = fmaf(cv[6],  a1.z, d1); d1 = fmaf(cv[7],  a1.w, d1);
            d2 = fmaf(cv[8],  a2.x, d2); d2 = fmaf(cv[9],  a2.y, d2);
            d2 = fmaf(cv[10], a2.z, d2); d2 = fmaf(cv[11], a2.w, d2);
            d3 = fmaf(cv[12], a3.x, d3); d3 = fmaf(cv[13], a3.y, d3);
            d3 = fmaf(cv[14], a3.z, d3); d3 = fmaf(cv[15], a3.w, d3);
            lg[k] = ((d0 + d1) + (d2 + d3)) * INV_TEMP;
            mk[k] = (labels[nn * HWSZ + off[k]] == lc[k]);
            S += mk[k] ? __expf(lg[k]) : 0.f;
        }
        float logS = __logf(S + EPSV);
#pragma unroll
        for (int k = 0; k < NB; k++)
            sum += mk[k] ? (logS - lg[k]) : __int_as_float(0x7f800000);
    }
    float val = sum * (1.0f / (16.0f * 65536.0f));

    __shared__ float red[256];
    int t = threadIdx.x;
    red[t] = val;
    __syncthreads();
#pragma unroll 1
    for (int s = 128; s > 0; s >>= 1) {
        if (t < s) red[t] += red[t + s];
        __syncthreads();
    }
    if (t == 0) g_dp[blockIdx.x] = red[0];
}

// ---------------------------------------------------------------------------
// Kernel 4: final deterministic reduction -> scalar
// ---------------------------------------------------------------------------
__global__ void k_reduce(float* __restrict__ out) {
    __shared__ float red[512];
    int t = threadIdx.x;
    float v = g_lp[t];
    if (t < 256) v += g_dp[t];
    red[t] = v;
    __syncthreads();
#pragma unroll 1
    for (int s = 256; s > 0; s >>= 1) {
        if (t < s) red[t] += red[t + s];
        __syncthreads();
    }
    if (t == 0) out[0] = red[0];
}

// ---------------------------------------------------------------------------
extern "C" void kernel_launch(void* const* d_in, const int* in_sizes, int n_in,
                              void* d_out, int out_size) {
    const float* feat   = (const float*)d_in[0];
    const int*   labels = (const int*)d_in[1];
    const int*   dirs   = (const int*)d_in[2];
    float* out = (float*)d_out;

    const int smem = 12 * 4096 * 4 + 3072 * 4;   // 196608 + 12288 = 208896 B
    cudaFuncSetAttribute(k_local, cudaFuncAttributeMaxDynamicSharedMemorySize, smem);

    k_norm<<<1024, 256>>>(feat);
    k_local<<<512, 512, smem>>>(labels);
    k_dir<<<256, 256>>>(labels, dirs);
    k_reduce<<<1, 512>>>(out);
}

// round 2
// speedup vs baseline: 1.2345x; 1.2345x over previous
#include <cuda_runtime.h>
#include <math.h>

// Problem constants
#define NB   4
#define CH   16
#define HWSZ 65536
#define EPSV 1e-6f
#define LOG2E_T 14.4269504089f   // (1/TEMP) * log2(e) = 10 * 1.442695

typedef unsigned long long u64;

// Channels-last normalized features: [n][i][j][c], 4*65536*16 floats = 16 MB
__device__ float g_fn[(size_t)NB * HWSZ * CH];
__device__ float g_lp[512];
__device__ float g_dp[256];
__device__ unsigned int g_ctr = 0;

// ---------------- packed f32x2 helpers ----------------
__device__ __forceinline__ u64 f2mul(u64 a, u64 b) {
    u64 d; asm("mul.rn.f32x2 %0,%1,%2;" : "=l"(d) : "l"(a), "l"(b)); return d;
}
__device__ __forceinline__ u64 f2fma(u64 a, u64 b, u64 c) {
    u64 d; asm("fma.rn.f32x2 %0,%1,%2,%3;" : "=l"(d) : "l"(a), "l"(b), "l"(c)); return d;
}
__device__ __forceinline__ u64 f2add(u64 a, u64 b) {
    u64 d; asm("add.rn.f32x2 %0,%1,%2;" : "=l"(d) : "l"(a), "l"(b)); return d;
}
__device__ __forceinline__ float f2hsum(u64 v) {
    float lo, hi; asm("mov.b64 {%0,%1},%2;" : "=f"(lo), "=f"(hi) : "l"(v));
    return lo + hi;
}
__device__ __forceinline__ float ex2f(float x) {
    float r; asm("ex2.approx.ftz.f32 %0,%1;" : "=f"(r) : "f"(x)); return r;
}
__device__ __forceinline__ float dot16(const u64* a, const u64* b) {
    u64 p = f2mul(a[0], b[0]);
    u64 q = f2mul(a[1], b[1]);
    p = f2fma(a[2], b[2], p);  q = f2fma(a[3], b[3], q);
    p = f2fma(a[4], b[4], p);  q = f2fma(a[5], b[5], q);
    p = f2fma(a[6], b[6], p);  q = f2fma(a[7], b[7], q);
    return f2hsum(f2add(p, q));
}

// ---------------------------------------------------------------------------
// Kernel 1: L2-normalize over C and transpose NCHW -> N(HW)C (channels-last)
// ---------------------------------------------------------------------------
__global__ void k_norm(const float* __restrict__ f) {
    int idx = blockIdx.x * blockDim.x + threadIdx.x;
    int n   = idx >> 16;
    int pix = idx & 65535;
    const float* b = f + (size_t)n * CH * HWSZ + pix;
    float v[CH];
    float ss = 0.f;
#pragma unroll
    for (int c = 0; c < CH; c++) {
        v[c] = b[(size_t)c * HWSZ];
        ss = fmaf(v[c], v[c], ss);
    }
    float inv = 1.0f / fmaxf(sqrtf(ss), 1e-12f);
    float4* o = (float4*)(g_fn + (size_t)idx * CH);
#pragma unroll
    for (int c4 = 0; c4 < 4; c4++) {
        o[c4] = make_float4(v[c4*4+0]*inv, v[c4*4+1]*inv,
                            v[c4*4+2]*inv, v[c4*4+3]*inv);
    }
}

// ---------------------------------------------------------------------------
// Kernel 2: local 11x11 term. Block = (n, 2 center rows), 256 threads.
// Each thread owns BOTH center rows at column j (TI=2): every neighbor vector
// loaded once from smem serves two dot products.
// ---------------------------------------------------------------------------
__global__ void __launch_bounds__(256, 1)
k_local(const int* __restrict__ labels) {
    extern __shared__ float sm[];
    float* sF = sm;                      // 12 rows * 256 px * 16c floats
    int*   sL = (int*)(sm + 12 * 4096);  // 12 * 256 ints

    const int bx = blockIdx.x;           // 0..511
    const int n  = bx >> 7;
    const int i0 = (bx & 127) << 1;
    const int t  = threadIdx.x;          // j

    // ---- load halo tile (rows i0-5 .. i0+6), chunk-XOR swizzled ----
    {
        const float4* src = (const float4*)(g_fn + (size_t)n * HWSZ * CH);
#pragma unroll
        for (int k = 0; k < 48; k++) {
            int lin = t + (k << 8);          // 0..12287 float4s
            int rr  = lin >> 10;
            int row = i0 - 5 + rr;
            if ((unsigned)row < 256u) {
                int pxc = lin & 1023;
                int px  = pxc >> 2;
                int c4  = pxc & 3;
                float4 v = src[((row << 8) + px) * 4 + c4];
                int c4s = c4 ^ ((px >> 1) & 3);
                *(float4*)&sF[(rr << 12) + (px << 4) + (c4s << 2)] = v;
            }
        }
        const int* ls = labels + n * HWSZ;
#pragma unroll
        for (int k = 0; k < 12; k++) {
            int lin = t + (k << 8);
            int rr = lin >> 8, px = lin & 255;
            int row = i0 - 5 + rr;
            sL[lin] = ((unsigned)row < 256u) ? ls[(row << 8) + px]
                                             : (int)0x80000000;
        }
    }
    __syncthreads();

    const int j = t;
    const int s3c = (j >> 1) & 3;

    // center vectors for both rows (slots 5 and 6)
    u64 cv0[8], cv1[8];
#pragma unroll
    for (int c4 = 0; c4 < 4; c4++) {
        ulonglong2 a = *(const ulonglong2*)&sF[(5 << 12) + (j << 4) + ((c4 ^ s3c) << 2)];
        cv0[c4*2] = a.x; cv0[c4*2+1] = a.y;
        ulonglong2 b = *(const ulonglong2*)&sF[(6 << 12) + (j << 4) + ((c4 ^ s3c) << 2)];
        cv1[c4*2] = b.x; cv1[c4*2+1] = b.y;
    }
    const int clab0 = sL[(5 << 8) + j];
    const int clab1 = sL[(6 << 8) + j];

    float S0 = 0.f, D0 = 0.f, M0 = 0.f;
    float S1 = 0.f, D1 = 0.f, M1 = 0.f;

#pragma unroll 1
    for (int rr = 0; rr < 12; rr++) {
        int row = i0 - 5 + rr;
        if ((unsigned)row >= 256u) continue;        // warp-uniform
        const float mr0 = (rr <= 10) ? 1.0f : 0.0f; // slot feeds center0?
        const float mr1 = (rr >= 1)  ? 1.0f : 0.0f; // slot feeds center1?
        const float* rowF = &sF[rr << 12];
        const int*   rowL = &sL[rr << 8];
#pragma unroll
        for (int q = -5; q <= 5; q++) {
            int jq  = j + q;
            bool vld = (unsigned)jq < 256u;
            int jc  = vld ? jq : (jq < 0 ? 0 : 255);
            int s3  = (jc >> 1) & 3;
            const float* nb = &rowF[jc << 4];
            ulonglong2 x0 = *(const ulonglong2*)(nb + ((0 ^ s3) << 2));
            ulonglong2 x1 = *(const ulonglong2*)(nb + ((1 ^ s3) << 2));
            ulonglong2 x2 = *(const ulonglong2*)(nb + ((2 ^ s3) << 2));
            ulonglong2 x3 = *(const ulonglong2*)(nb + ((3 ^ s3) << 2));
            u64 nv[8] = {x0.x, x0.y, x1.x, x1.y, x2.x, x2.y, x3.x, x3.y};

            float dt0 = dot16(cv0, nv);
            float dt1 = dot16(cv1, nv);
            int   lb  = rowL[jc];

            float e0 = ex2f(dt0 * LOG2E_T);
            float e1 = ex2f(dt1 * LOG2E_T);
            float m0 = (vld && lb == clab0) ? mr0 : 0.f;
            float m1 = (vld && lb == clab1) ? mr1 : 0.f;
            S0 = fmaf(m0, e0, S0);  D0 = fmaf(m0, dt0, D0);  M0 += m0;
            S1 = fmaf(m1, e1, S1);  D1 = fmaf(m1, dt1, D1);  M1 += m1;
        }
    }

    // contrib = M*log(S+eps) - 10*D
    float c0 = fmaf(M0, __logf(S0 + EPSV), -10.0f * D0);
    float c1 = fmaf(M1, __logf(S1 + EPSV), -10.0f * D1);
    int ci0 = i0, ci1 = i0 + 1;
    float ch0 = (float)(11 - max(0, 5 - ci0) - max(0, ci0 - 250));
    float ch1 = (float)(11 - max(0, 5 - ci1) - max(0, ci1 - 250));
    float cw  = (float)(11 - max(0, 5 - j)   - max(0, j   - 250));
    float val = (c0 / (ch0 * cw) + c1 / (ch1 * cw)) * (1.0f / (4.0f * 65536.0f));

    // deterministic block reduction via shuffles
    __syncthreads();
#pragma unroll
    for (int o = 16; o > 0; o >>= 1) val += __shfl_down_sync(0xffffffffu, val, o);
    if ((t & 31) == 0) sm[t >> 5] = val;
    __syncthreads();
    if (t < 32) {
        float x = (t < 8) ? sm[t] : 0.f;
#pragma unroll
        for (int o = 4; o > 0; o >>= 1) x += __shfl_down_sync(0xffffffffu, x, o);
        if (t == 0) g_lp[bx] = x;
    }
}

// ---------------------------------------------------------------------------
// Kernel 3: directional term + folded final reduction (last-block pattern).
// ---------------------------------------------------------------------------
__global__ void k_dir(const int* __restrict__ labels,
                      const int* __restrict__ dirs,
                      float* __restrict__ out) {
    int tid = blockIdx.x * 256 + threadIdx.x;   // pixel index i*256+j
    int i = tid >> 8, j = tid & 255;
    int t = threadIdx.x;

    int off[NB], lc[NB];
#pragma unroll
    for (int k = 0; k < NB; k++) {
        int di = dirs[(k * 2 + 0) * HWSZ + tid];
        int dj = dirs[(k * 2 + 1) * HWSZ + tid];
        off[k] = ((i + di) << 8) + (j + dj);
        lc[k]  = labels[k * HWSZ + tid];
    }

    float sum = 0.f;
#pragma unroll 1
    for (int nn = 0; nn < NB; nn++) {
        const u64* base2 = (const u64*)(g_fn + (size_t)nn * HWSZ * CH);
        u64 cv[8];
        {
            const ulonglong2* c2 = (const ulonglong2*)(base2 + (size_t)tid * 8);
            ulonglong2 a0 = c2[0], a1 = c2[1], a2 = c2[2], a3 = c2[3];
            cv[0]=a0.x; cv[1]=a0.y; cv[2]=a1.x; cv[3]=a1.y;
            cv[4]=a2.x; cv[5]=a2.y; cv[6]=a3.x; cv[7]=a3.y;
        }
        float dt[NB]; bool mk[NB]; float S = 0.f;
#pragma unroll
        for (int k = 0; k < NB; k++) {
            const ulonglong2* n2 = (const ulonglong2*)(base2 + (size_t)off[k] * 8);
            ulonglong2 a0 = n2[0], a1 = n2[1], a2 = n2[2], a3 = n2[3];
            u64 nv[8] = {a0.x, a0.y, a1.x, a1.y, a2.x, a2.y, a3.x, a3.y};
            dt[k] = dot16(cv, nv);
            mk[k] = (labels[nn * HWSZ + off[k]] == lc[k]);
            S += mk[k] ? ex2f(dt[k] * LOG2E_T) : 0.f;
        }
        float logS = __logf(S + EPSV);
#pragma unroll
        for (int k = 0; k < NB; k++)
            sum += mk[k] ? (logS - 10.0f * dt[k]) : __int_as_float(0x7f800000);
    }
    float val = sum * (1.0f / (16.0f * 65536.0f));

    // block reduce (shuffles, deterministic)
    __shared__ float wred[8];
    __shared__ bool  slast;
#pragma unroll
    for (int o = 16; o > 0; o >>= 1) val += __shfl_down_sync(0xffffffffu, val, o);
    if ((t & 31) == 0) wred[t >> 5] = val;
    __syncthreads();
    if (t < 32) {
        float x = (t < 8) ? wred[t] : 0.f;
#pragma unroll
        for (int o = 4; o > 0; o >>= 1) x += __shfl_down_sync(0xffffffffu, x, o);
        if (t == 0) {
            g_dp[blockIdx.x] = x;
            __threadfence();
            unsigned old = atomicAdd(&g_ctr, 1u);
            slast = (old == 255u);
        }
    }
    __syncthreads();

    if (slast) {  // last finishing block: deterministic final sum
        float v = g_lp[t] + g_lp[t + 256] + g_dp[t];
#pragma unroll
        for (int o = 16; o > 0; o >>= 1) v += __shfl_down_sync(0xffffffffu, v, o);
        if ((t & 31) == 0) wred[t >> 5] = v;
        __syncthreads();
        if (t == 0) {
            float s = 0.f;
#pragma unroll
            for (int w = 0; w < 8; w++) s += wred[w];
            out[0] = s;
            g_ctr = 0;   // reset for next graph replay
        }
    }
}

// ---------------------------------------------------------------------------
extern "C" void kernel_launch(void* const* d_in, const int* in_sizes, int n_in,
                              void* d_out, int out_size) {
    const float* feat   = (const float*)d_in[0];
    const int*   labels = (const int*)d_in[1];
    const int*   dirs   = (const int*)d_in[2];
    float* out = (float*)d_out;

    const int smem = 12 * 4096 * 4 + 3072 * 4;   // 208896 B
    cudaFuncSetAttribute(k_local, cudaFuncAttributeMaxDynamicSharedMemorySize, smem);

    k_norm<<<1024, 256>>>(feat);
    k_local<<<512, 256, smem>>>(labels);
    k_dir<<<256, 256>>>(labels, dirs, out);
}

// round 3
// speedup vs baseline: 1.6658x; 1.3493x over previous
#include <cuda_runtime.h>
#include <cuda_fp16.h>
#include <math.h>

#define NB   4
#define CH   16
#define HWSZ 65536
#define EPSV 1e-6f
#define LOG2E_T 14.4269504089f   // (1/TEMP) * log2(e)

typedef unsigned long long u64;
typedef unsigned int u32;

// Channels-last normalized features in fp16: [n][pix][16 halves] = 8 MB
__device__ u32 g_fnh[(size_t)NB * HWSZ * 8];
__device__ float g_lp[512];
__device__ float g_dp[256];
__device__ unsigned int g_ctr = 0;

// ---------------- packed f32x2 helpers ----------------
__device__ __forceinline__ u64 f2mul(u64 a, u64 b) {
    u64 d; asm("mul.rn.f32x2 %0,%1,%2;" : "=l"(d) : "l"(a), "l"(b)); return d;
}
__device__ __forceinline__ u64 f2fma(u64 a, u64 b, u64 c) {
    u64 d; asm("fma.rn.f32x2 %0,%1,%2,%3;" : "=l"(d) : "l"(a), "l"(b), "l"(c)); return d;
}
__device__ __forceinline__ u64 f2add(u64 a, u64 b) {
    u64 d; asm("add.rn.f32x2 %0,%1,%2;" : "=l"(d) : "l"(a), "l"(b)); return d;
}
__device__ __forceinline__ float f2hsum(u64 v) {
    float lo, hi; asm("mov.b64 {%0,%1},%2;" : "=f"(lo), "=f"(hi) : "l"(v));
    return lo + hi;
}
__device__ __forceinline__ u64 pack2(float lo, float hi) {
    u64 d; asm("mov.b64 %0,{%1,%2};" : "=l"(d) : "f"(lo), "f"(hi)); return d;
}
__device__ __forceinline__ float ex2f(float x) {
    float r; asm("ex2.approx.ftz.f32 %0,%1;" : "=f"(r) : "f"(x)); return r;
}
__device__ __forceinline__ float dot16(const u64* a, const u64* b) {
    u64 p = f2mul(a[0], b[0]);
    u64 q = f2mul(a[1], b[1]);
    p = f2fma(a[2], b[2], p);  q = f2fma(a[3], b[3], q);
    p = f2fma(a[4], b[4], p);  q = f2fma(a[5], b[5], q);
    p = f2fma(a[6], b[6], p);  q = f2fma(a[7], b[7], q);
    return f2hsum(f2add(p, q));
}
// 16 halves (two uint4) -> 8 packed f32x2
__device__ __forceinline__ void cvt16(uint4 a, uint4 b, u64 nv[8]) {
    float2 f;
    f = __half22float2(*(const __half2*)&a.x); nv[0] = pack2(f.x, f.y);
    f = __half22float2(*(const __half2*)&a.y); nv[1] = pack2(f.x, f.y);
    f = __half22float2(*(const __half2*)&a.z); nv[2] = pack2(f.x, f.y);
    f = __half22float2(*(const __half2*)&a.w); nv[3] = pack2(f.x, f.y);
    f = __half22float2(*(const __half2*)&b.x); nv[4] = pack2(f.x, f.y);
    f = __half22float2(*(const __half2*)&b.y); nv[5] = pack2(f.x, f.y);
    f = __half22float2(*(const __half2*)&b.z); nv[6] = pack2(f.x, f.y);
    f = __half22float2(*(const __half2*)&b.w); nv[7] = pack2(f.x, f.y);
}
// load 16-half vector from a parity sub-array (idx in [0,127]) with XOR swizzle
__device__ __forceinline__ void loadvec(const char* parityBase, int idx, u64 nv[8]) {
    int sw = ((idx >> 2) & 1) << 4;
    const char* p = parityBase + (idx << 5);
    uint4 a = *(const uint4*)(p + sw);
    uint4 b = *(const uint4*)(p + (16 ^ sw));
    cvt16(a, b, nv);
}

// ---------------------------------------------------------------------------
// Kernel 1: L2-normalize over C, transpose NCHW -> N(HW)C, quantize to fp16
// ---------------------------------------------------------------------------
__global__ void k_norm(const float* __restrict__ f) {
    int idx = blockIdx.x * blockDim.x + threadIdx.x;  // 0 .. N*HW-1
    int n   = idx >> 16;
    int pix = idx & 65535;
    const float* b = f + (size_t)n * CH * HWSZ + pix;
    float v[CH];
    float ss = 0.f;
#pragma unroll
    for (int c = 0; c < CH; c++) {
        v[c] = b[(size_t)c * HWSZ];
        ss = fmaf(v[c], v[c], ss);
    }
    float inv = 1.0f / fmaxf(sqrtf(ss), 1e-12f);
    u32 h[8];
#pragma unroll
    for (int c2 = 0; c2 < 8; c2++) {
        __half2 hh = __floats2half2_rn(v[c2*2] * inv, v[c2*2+1] * inv);
        h[c2] = *(u32*)&hh;
    }
    uint4* o = (uint4*)(g_fnh + (size_t)idx * 8);
    o[0] = make_uint4(h[0], h[1], h[2], h[3]);
    o[1] = make_uint4(h[4], h[5], h[6], h[7]);
}

// ---------------------------------------------------------------------------
// Kernel 2: local 11x11 term. Block = (n, 2 center rows), 128 threads.
// Thread t owns pixels (i0, 2t), (i0, 2t+1), (i0+1, 2t), (i0+1, 2t+1).
// Smem: 12 halo rows, fp16 channels-last, even/odd pixel deinterleave with
// chunk XOR swizzle -> conflict-free LDS.128 at lane stride 1.
// ---------------------------------------------------------------------------
__global__ void __launch_bounds__(128, 2)
k_local(const int* __restrict__ labels) {
    extern __shared__ char sm[];
    char* sF   = sm;                    // 12 rows * 8192 B (even 4096 | odd 4096)
    int*  sLab = (int*)(sm + 98304);    // 12 rows * 256 ints (even 128 | odd 128)

    const int bx = blockIdx.x;          // 0..511
    const int n  = bx >> 7;
    const int i0 = (bx & 127) << 1;
    const int t  = threadIdx.x;         // 0..127, col pair (2t, 2t+1)

    // ---- fill halo (rows i0-5 .. i0+6) ----
    {
        const uint4* src = (const uint4*)(g_fnh + (size_t)n * HWSZ * 8);
#pragma unroll
        for (int k = 0; k < 48; k++) {
            int lin = t + (k << 7);          // 0..6143 uint4s
            int rr  = lin >> 9;              // 512 uint4 per row slot
            int row = i0 - 5 + rr;
            if ((unsigned)row < 256u) {
                int w = lin & 511;
                int parity = w >> 8;
                int idx = w & 255;
                int e = idx >> 1, ch = idx & 1;
                int px = (e << 1) + parity;
                uint4 v = src[(size_t)((row << 8) + px) * 2 + ch];
                *(uint4*)(sF + (rr << 13) + (parity << 12) + (e << 5)
                          + ((ch ^ ((e >> 2) & 1)) << 4)) = v;
            }
        }
        const int* ls = labels + n * HWSZ;
#pragma unroll
        for (int k = 0; k < 24; k++) {
            int lin = t + (k << 7);          // 0..3071
            int rr = lin >> 8;
            int px = lin & 255;
            int row = i0 - 5 + rr;
            int parity = px & 1, e = px >> 1;
            sLab[(rr << 8) + (parity << 7) + e] =
                ((unsigned)row < 256u) ? ls[(row << 8) + px] : (int)0x80000000;
        }
    }
    __syncthreads();

    // ---- center vectors (slots 5, 6; even idx t, odd idx t) ----
    u64 cv00[8], cv01[8], cv10[8], cv11[8];   // [row][colparity]
    loadvec(sF + (5 << 13),        t, cv00);
    loadvec(sF + (5 << 13) + 4096, t, cv01);
    loadvec(sF + (6 << 13),        t, cv10);
    loadvec(sF + (6 << 13) + 4096, t, cv11);
    const int clab00 = sLab[(5 << 8) + t];
    const int clab01 = sLab[(5 << 8) + 128 + t];
    const int clab10 = sLab[(6 << 8) + t];
    const int clab11 = sLab[(6 << 8) + 128 + t];

    float S00=0,S01=0,S10=0,S11=0;
    float D00=0,D01=0,D10=0,D11=0;
    float M00=0,M01=0,M10=0,M11=0;

#pragma unroll 1
    for (int rr = 0; rr < 12; rr++) {
        int row = i0 - 5 + rr;
        if ((unsigned)row >= 256u) continue;   // warp-uniform
        const float mr0 = (rr <= 10) ? 1.f : 0.f;
        const float mr1 = (rr >= 1)  ? 1.f : 0.f;
        const char* rowE = sF + (rr << 13);
        const char* rowO = rowE + 4096;
        const int* labE = sLab + (rr << 8);
        const int* labO = labE + 128;

        // even-pixel neighbors: jc = 2(t-2+u), u=0..5; c1 always, c0 unless u==5
#pragma unroll
        for (int u = 0; u < 6; u++) {
            int e = t - 2 + u;
            bool vld = (unsigned)e < 128u;
            int ec = vld ? e : (e < 0 ? 0 : 127);
            u64 nv[8]; loadvec(rowE, ec, nv);
            int lb = labE[ec];
            float dt01 = dot16(cv01, nv);
            float dt11 = dot16(cv11, nv);
            float e01 = ex2f(dt01 * LOG2E_T);
            float e11 = ex2f(dt11 * LOG2E_T);
            float a0 = (vld && lb == clab01) ? mr0 : 0.f;
            float a1 = (vld && lb == clab11) ? mr1 : 0.f;
            S01 = fmaf(a0, e01, S01); D01 = fmaf(a0, dt01, D01); M01 += a0;
            S11 = fmaf(a1, e11, S11); D11 = fmaf(a1, dt11, D11); M11 += a1;
            if (u != 5) {
                float dt00 = dot16(cv00, nv);
                float dt10 = dot16(cv10, nv);
                float e00 = ex2f(dt00 * LOG2E_T);
                float e10 = ex2f(dt10 * LOG2E_T);
                float b0 = (vld && lb == clab00) ? mr0 : 0.f;
                float b1 = (vld && lb == clab10) ? mr1 : 0.f;
                S00 = fmaf(b0, e00, S00); D00 = fmaf(b0, dt00, D00); M00 += b0;
                S10 = fmaf(b1, e10, S10); D10 = fmaf(b1, dt10, D10); M10 += b1;
            }
        }
        // odd-pixel neighbors: jc = 2(t-3+u)+1, u=0..5; c0 always, c1 unless u==0
#pragma unroll
        for (int u = 0; u < 6; u++) {
            int m = t - 3 + u;
            bool vld = (unsigned)m < 128u;
            int mc = vld ? m : (m < 0 ? 0 : 127);
            u64 nv[8]; loadvec(rowO, mc, nv);
            int lb = labO[mc];
            float dt00 = dot16(cv00, nv);
            float dt10 = dot16(cv10, nv);
            float e00 = ex2f(dt00 * LOG2E_T);
            float e10 = ex2f(dt10 * LOG2E_T);
            float b0 = (vld && lb == clab00) ? mr0 : 0.f;
            float b1 = (vld && lb == clab10) ? mr1 : 0.f;
            S00 = fmaf(b0, e00, S00); D00 = fmaf(b0, dt00, D00); M00 += b0;
            S10 = fmaf(b1, e10, S10); D10 = fmaf(b1, dt10, D10); M10 += b1;
            if (u != 0) {
                float dt01 = dot16(cv01, nv);
                float dt11 = dot16(cv11, nv);
                float e01 = ex2f(dt01 * LOG2E_T);
                float e11 = ex2f(dt11 * LOG2E_T);
                float a0 = (vld && lb == clab01) ? mr0 : 0.f;
                float a1 = (vld && lb == clab11) ? mr1 : 0.f;
                S01 = fmaf(a0, e01, S01); D01 = fmaf(a0, dt01, D01); M01 += a0;
                S11 = fmaf(a1, e11, S11); D11 = fmaf(a1, dt11, D11); M11 += a1;
            }
        }
    }

    // contrib = M*log(S+eps) - 10*D, weighted by 1/(count) /(N*HW)
    float c00 = fmaf(M00, __logf(S00 + EPSV), -10.f * D00);
    float c01 = fmaf(M01, __logf(S01 + EPSV), -10.f * D01);
    float c10 = fmaf(M10, __logf(S10 + EPSV), -10.f * D10);
    float c11 = fmaf(M11, __logf(S11 + EPSV), -10.f * D11);
    int ci0 = i0, ci1 = i0 + 1, j0 = 2 * t, j1 = 2 * t + 1;
    float ch0 = (float)(11 - max(0, 5 - ci0) - max(0, ci0 - 250));
    float ch1 = (float)(11 - max(0, 5 - ci1) - max(0, ci1 - 250));
    float cw0 = (float)(11 - max(0, 5 - j0)  - max(0, j0  - 250));
    float cw1 = (float)(11 - max(0, 5 - j1)  - max(0, j1  - 250));
    float val = (c00 / (ch0 * cw0) + c01 / (ch0 * cw1)
               + c10 / (ch1 * cw0) + c11 / (ch1 * cw1)) * (1.0f / (4.0f * 65536.0f));

    // deterministic block reduction
    __shared__ float wred[4];
#pragma unroll
    for (int o = 16; o > 0; o >>= 1) val += __shfl_down_sync(0xffffffffu, val, o);
    if ((t & 31) == 0) wred[t >> 5] = val;
    __syncthreads();
    if (t == 0) g_lp[bx] = (wred[0] + wred[1]) + (wred[2] + wred[3]);
}

// ---------------------------------------------------------------------------
// Kernel 3: directional term + folded final reduction (last-block pattern).
// ---------------------------------------------------------------------------
__global__ void k_dir(const int* __restrict__ labels,
                      const int* __restrict__ dirs,
                      float* __restrict__ out) {
    int tid = blockIdx.x * 256 + threadIdx.x;   // pixel index i*256+j
    int i = tid >> 8, j = tid & 255;
    int t = threadIdx.x;

    int off[NB], lc[NB];
#pragma unroll
    for (int k = 0; k < NB; k++) {
        int di = dirs[(k * 2 + 0) * HWSZ + tid];
        int dj = dirs[(k * 2 + 1) * HWSZ + tid];
        off[k] = ((i + di) << 8) + (j + dj);
        lc[k]  = labels[k * HWSZ + tid];
    }

    float sum = 0.f;
#pragma unroll 1
    for (int nn = 0; nn < NB; nn++) {
        const uint4* base = (const uint4*)(g_fnh + (size_t)nn * HWSZ * 8);
        u64 cv[8];
        cvt16(base[(size_t)tid * 2], base[(size_t)tid * 2 + 1], cv);
        float dt[NB]; bool mk[NB]; float S = 0.f;
#pragma unroll
        for (int k = 0; k < NB; k++) {
            u64 nv[8];
            cvt16(base[(size_t)off[k] * 2], base[(size_t)off[k] * 2 + 1], nv);
            dt[k] = dot16(cv, nv);
            mk[k] = (labels[nn * HWSZ + off[k]] == lc[k]);
            S += mk[k] ? ex2f(dt[k] * LOG2E_T) : 0.f;
        }
        float logS = __logf(S + EPSV);
#pragma unroll
        for (int k = 0; k < NB; k++)
            sum += mk[k] ? (logS - 10.0f * dt[k]) : __int_as_float(0x7f800000);
    }
    float val = sum * (1.0f / (16.0f * 65536.0f));

    // block reduce (deterministic), then last block folds the final sum
    __shared__ float wred[8];
    __shared__ bool  slast;
#pragma unroll
    for (int o = 16; o > 0; o >>= 1) val += __shfl_down_sync(0xffffffffu, val, o);
    if ((t & 31) == 0) wred[t >> 5] = val;
    __syncthreads();
    if (t < 32) {
        float x = (t < 8) ? wred[t] : 0.f;
#pragma unroll
        for (int o = 4; o > 0; o >>= 1) x += __shfl_down_sync(0xffffffffu, x, o);
        if (t == 0) {
            g_dp[blockIdx.x] = x;
            __threadfence();
            unsigned old = atomicAdd(&g_ctr, 1u);
            slast = (old == 255u);
        }
    }
    __syncthreads();

    if (slast) {
        float v = g_lp[t] + g_lp[t + 256] + g_dp[t];
#pragma unroll
        for (int o = 16; o > 0; o >>= 1) v += __shfl_down_sync(0xffffffffu, v, o);
        if ((t & 31) == 0) wred[t >> 5] = v;
        __syncthreads();
        if (t == 0) {
            float s = 0.f;
#pragma unroll
            for (int w = 0; w < 8; w++) s += wred[w];
            out[0] = s;
            g_ctr = 0;   // reset for next graph replay
        }
    }
}

// ---------------------------------------------------------------------------
extern "C" void kernel_launch(void* const* d_in, const int* in_sizes, int n_in,
                              void* d_out, int out_size) {
    const float* feat   = (const float*)d_in[0];
    const int*   labels = (const int*)d_in[1];
    const int*   dirs   = (const int*)d_in[2];
    float* out = (float*)d_out;

    const int smem = 98304 + 12288;   // 110,592 B -> 2 blocks/SM
    cudaFuncSetAttribute(k_local, cudaFuncAttributeMaxDynamicSharedMemorySize, smem);

    k_norm<<<1024, 256>>>(feat);
    k_local<<<512, 128, smem>>>(labels);
    k_dir<<<256, 256>>>(labels, dirs, out);
}